// round 16
// baseline (speedup 1.0000x reference)
#include <cuda_runtime.h>
#include <cuda_fp16.h>
#include <stdint.h>
#include <math.h>

// ---------------------------------------------------------------------------
// Problem constants
// ---------------------------------------------------------------------------
#define BATCH 4
#define SEQ   2048
#define DIM   768
#define NHEAD 12
#define HD    64
#define NA    64
#define NB    32
#define MROWS 8192
#define KD    768
#define NAB   1152
#define NPOOL 256

// ---------------------------------------------------------------------------
// Static scratch
// ---------------------------------------------------------------------------
__device__ __align__(256) __half g_Yh[MROWS * NAB];      // x@[Wa|Wb] fp16
__device__ __align__(256) __half g_P[MROWS * KD];        // normalized exp-scores
__device__ __align__(256) __half g_Vt[BATCH * KD * KD];  // per-batch Vtilde [n][k]
__device__ __align__(256) float  g_VBAR[NPOOL * DIM];    // pooled-x @ Wv
__device__ __align__(256) __half g_Xh[MROWS * KD];
__device__ __align__(256) __half g_Xbar[NPOOL * KD];
__device__ __align__(256) __half g_W1[NAB * KD];
__device__ __align__(256) __half g_Wv[DIM * KD];
__device__ __align__(256) __half g_Wp[DIM * KD];

// software grid barrier state (zero-initialized; replay-safe by design)
__device__ int g_bar_arrive[3];
__device__ int g_bar_release[3];

#define GGRID 148
#define GTHR  512

// ---------------------------------------------------------------------------
// PTX helpers
// ---------------------------------------------------------------------------
__device__ __forceinline__ uint32_t smem_u32(const void* p) {
    uint32_t a;
    asm("{ .reg .u64 t; cvta.to.shared.u64 t, %1; cvt.u32.u64 %0, t; }"
        : "=r"(a) : "l"(p));
    return a;
}

#define CP16(saddr, gptr) \
    asm volatile("cp.async.cg.shared.global [%0], [%1], 16;" \
                 :: "r"(saddr), "l"(gptr) : "memory")
#define CP_COMMIT() asm volatile("cp.async.commit_group;" ::: "memory")
#define CP_WAIT1()  asm volatile("cp.async.wait_group 1;" ::: "memory")
#define CP_WAIT0()  asm volatile("cp.async.wait_group 0;" ::: "memory")

#define LDM4(r, addr) \
    asm volatile("ldmatrix.sync.aligned.m8n8.x4.shared.b16 {%0,%1,%2,%3}, [%4];" \
                 : "=r"((r)[0]), "=r"((r)[1]), "=r"((r)[2]), "=r"((r)[3]) \
                 : "r"(addr))

#define MMA(c, a, b0, b1) \
    asm volatile("mma.sync.aligned.m16n8k16.row.col.f32.f16.f16.f32 " \
                 "{%0,%1,%2,%3}, {%4,%5,%6,%7}, {%8,%9}, {%0,%1,%2,%3};" \
                 : "+f"((c)[0]), "+f"((c)[1]), "+f"((c)[2]), "+f"((c)[3]) \
                 : "r"((a)[0]), "r"((a)[1]), "r"((a)[2]), "r"((a)[3]), \
                   "r"(b0), "r"(b1))

// ---------------------------------------------------------------------------
// Grid barrier: arrive-count + monotone release. relv = entry snapshot.
// Safe across CUDA-graph replays: last arriver resets the arrive counter;
// release increments monotonically and is compared against the snapshot.
// ---------------------------------------------------------------------------
__device__ __forceinline__ void grid_barrier(int i, int relv) {
    __syncthreads();
    if (threadIdx.x == 0) {
        __threadfence();
        const int v = atomicAdd(&g_bar_arrive[i], 1);
        if (v == GGRID - 1) {
            atomicExch(&g_bar_arrive[i], 0);
            __threadfence();
            atomicAdd(&g_bar_release[i], 1);
        } else {
            while (atomicAdd(&g_bar_release[i], 0) == relv)
                __nanosleep(64);
        }
        __threadfence();
    }
    __syncthreads();
}

// ---------------------------------------------------------------------------
// GEMM phase (persistent, fp32-acc). CTA 128x128, 16 warps (4Mx4N, 32x32).
// K-chunk 128 (two 64-k swizzled sub-buffers), 3-stage 64KB pipeline,
// prefetch distance 2, wait_group 1, one __syncthreads per chunk.
// mode0: tiles [0,576) A0@B0 -> C0 (Yh fp16, ld NAB); [576,588) A1@B1 -> C1 f32
// else : tiles [0,384) A0@B0_b + bias -> C0 f32 (B0 per batch, [N][K])
// ---------------------------------------------------------------------------
#define KC    128
#define NCHT  6
#define HBUF  16384
#define STG   (4 * HBUF)       // 64 KB
#define NSTG  3
#define GSMEM (NSTG * STG)     // 192 KB

#define SWZ(row, ch) (((uint32_t)(row) << 7) + ((((uint32_t)(ch)) ^ ((row) & 7)) << 4))

__device__ __forceinline__ void ld_chunk(
    uint32_t sb, const __half* __restrict__ Ag, const __half* __restrict__ Bg,
    int row0, int col0, int kc, int tid)
{
    const int rr = tid >> 2;
    const int c2 = (tid & 3) << 1;
    const uint32_t s0 = SWZ(rr, c2), s1 = SWZ(rr, c2 + 1);
    const __half* ap = Ag + (size_t)(row0 + rr) * KD + kc + c2 * 8;
    CP16(sb + s0,            ap);
    CP16(sb + s1,            ap + 8);
    CP16(sb + HBUF + s0,     ap + 64);
    CP16(sb + HBUF + s1,     ap + 72);
    const __half* bp = Bg + (size_t)(col0 + rr) * KD + kc + c2 * 8;
    CP16(sb + 2 * HBUF + s0, bp);
    CP16(sb + 2 * HBUF + s1, bp + 8);
    CP16(sb + 3 * HBUF + s0, bp + 64);
    CP16(sb + 3 * HBUF + s1, bp + 72);
}

__device__ void gemm_phase(
    bool mode0,
    const __half* __restrict__ A0, const __half* __restrict__ B0,
    void* __restrict__ C0v,
    const __half* __restrict__ A1, const __half* __restrict__ B1,
    float* __restrict__ C1,
    const float* __restrict__ bias, int ntiles,
    uint32_t sbase, int tid, int bid)
{
    const int wid  = tid >> 5;
    const int lane = tid & 31;
    const int m0 = (wid & 3) * 32;
    const int n0 = (wid >> 2) * 32;
    const int lr = lane & 15;
    const int lh = lane >> 4;
    const int r7 = lr & 7;

    const int tcount = (bid < ntiles) ? ((ntiles - 1 - bid) / GGRID + 1) : 0;
    if (tcount == 0) return;
    const int total_g = tcount * NCHT;

    auto tmap_load = [&](int t, const __half*& A, const __half*& B,
                         int& row0, int& col0) {
        if (mode0) {
            if (t < 576) { A = A0; B = B0; row0 = (t / 9) << 7; col0 = (t % 9) << 7; }
            else { int tt = t - 576; A = A1; B = B1;
                   row0 = (tt / 6) << 7; col0 = (tt % 6) << 7; }
        } else {
            row0 = (t / 6) << 7; col0 = (t % 6) << 7;
            A = A0; B = B0 + (size_t)(row0 >> 11) * KD * KD;
        }
    };

    uint32_t aRow[2], bRow[2];
    #pragma unroll
    for (int mt = 0; mt < 2; mt++)
        aRow[mt] = sbase + ((uint32_t)(m0 + mt * 16 + lr) << 7);
    #pragma unroll
    for (int nt = 0; nt < 2; nt++)
        bRow[nt] = sbase + 2 * HBUF + ((uint32_t)(n0 + nt * 16 + lr) << 7);

    float acc[2][4][4];
    #pragma unroll
    for (int i = 0; i < 2; i++)
        #pragma unroll
        for (int j = 0; j < 4; j++)
            #pragma unroll
            for (int q = 0; q < 4; q++) acc[i][j][q] = 0.f;

    const __half *Ap, *Bp;
    int rowp, colp;
    tmap_load(bid, Ap, Bp, rowp, colp);

    ld_chunk(sbase,       Ap, Bp, rowp, colp, 0,  tid);
    CP_COMMIT();
    ld_chunk(sbase + STG, Ap, Bp, rowp, colp, KC, tid);
    CP_COMMIT();

    int stage = 0;
    #pragma unroll 1
    for (int g = 0; g < total_g; g++) {
        CP_WAIT1();
        __syncthreads();

        const int g2 = g + 2;
        if (g2 < total_g) {
            const int c2 = g2 % NCHT;
            if (c2 == 0)
                tmap_load(bid + (g2 / NCHT) * GGRID, Ap, Bp, rowp, colp);
            int ws = stage + 2; if (ws >= NSTG) ws -= NSTG;
            ld_chunk(sbase + ws * STG, Ap, Bp, rowp, colp, c2 * KC, tid);
        }
        CP_COMMIT();

        const uint32_t so = (uint32_t)(stage * STG);
        #pragma unroll
        for (int kq = 0; kq < 8; kq++) {
            const uint32_t sub = so + (uint32_t)((kq >> 2) * HBUF);
            const uint32_t xp = sub + (uint32_t)((((kq & 3) * 2 + lh) ^ r7) << 4);
            uint32_t af[2][4], bf[2][4];
            #pragma unroll
            for (int mt = 0; mt < 2; mt++) LDM4(af[mt], aRow[mt] + xp);
            #pragma unroll
            for (int nt = 0; nt < 2; nt++) LDM4(bf[nt], bRow[nt] + xp);
            #pragma unroll
            for (int mt = 0; mt < 2; mt++)
                #pragma unroll
                for (int nt = 0; nt < 2; nt++)
                    #pragma unroll
                    for (int h = 0; h < 2; h++)
                        MMA(acc[mt][nt * 2 + h], af[mt], bf[nt][h], bf[nt][h + 2]);
        }

        if ((g % NCHT) == NCHT - 1) {
            const int t = bid + (g / NCHT) * GGRID;
            const int l4 = lane >> 2;
            const int l2 = (lane & 3) * 2;
            int row0, col0;
            if (mode0 && t < 576) {
                __half* C = (__half*)C0v;
                row0 = (t / 9) << 7; col0 = (t % 9) << 7;
                #pragma unroll
                for (int mt = 0; mt < 2; mt++)
                    #pragma unroll
                    for (int nn = 0; nn < 4; nn++) {
                        const int grow = row0 + m0 + mt * 16 + l4;
                        const int gcol = col0 + n0 + (nn >> 1) * 16 + (nn & 1) * 8 + l2;
                        *(__half2*)(C + (size_t)grow * NAB + gcol) =
                            __floats2half2_rn(acc[mt][nn][0], acc[mt][nn][1]);
                        *(__half2*)(C + (size_t)(grow + 8) * NAB + gcol) =
                            __floats2half2_rn(acc[mt][nn][2], acc[mt][nn][3]);
                        acc[mt][nn][0] = 0.f; acc[mt][nn][1] = 0.f;
                        acc[mt][nn][2] = 0.f; acc[mt][nn][3] = 0.f;
                    }
            } else if (mode0) {
                float* C = C1;
                const int tt = t - 576;
                row0 = (tt / 6) << 7; col0 = (tt % 6) << 7;
                #pragma unroll
                for (int mt = 0; mt < 2; mt++)
                    #pragma unroll
                    for (int nn = 0; nn < 4; nn++) {
                        const int grow = row0 + m0 + mt * 16 + l4;
                        const int gcol = col0 + n0 + (nn >> 1) * 16 + (nn & 1) * 8 + l2;
                        *(float2*)(C + (size_t)grow * DIM + gcol) =
                            make_float2(acc[mt][nn][0], acc[mt][nn][1]);
                        *(float2*)(C + (size_t)(grow + 8) * DIM + gcol) =
                            make_float2(acc[mt][nn][2], acc[mt][nn][3]);
                        acc[mt][nn][0] = 0.f; acc[mt][nn][1] = 0.f;
                        acc[mt][nn][2] = 0.f; acc[mt][nn][3] = 0.f;
                    }
            } else {
                float* C = (float*)C0v;
                row0 = (t / 6) << 7; col0 = (t % 6) << 7;
                #pragma unroll
                for (int mt = 0; mt < 2; mt++)
                    #pragma unroll
                    for (int nn = 0; nn < 4; nn++) {
                        const int grow = row0 + m0 + mt * 16 + l4;
                        const int gcol = col0 + n0 + (nn >> 1) * 16 + (nn & 1) * 8 + l2;
                        const float b0 = bias[gcol], b1 = bias[gcol + 1];
                        *(float2*)(C + (size_t)grow * DIM + gcol) =
                            make_float2(acc[mt][nn][0] + b0, acc[mt][nn][1] + b1);
                        *(float2*)(C + (size_t)(grow + 8) * DIM + gcol) =
                            make_float2(acc[mt][nn][2] + b0, acc[mt][nn][3] + b1);
                        acc[mt][nn][0] = 0.f; acc[mt][nn][1] = 0.f;
                        acc[mt][nn][2] = 0.f; acc[mt][nn][3] = 0.f;
                    }
            }
        }

        stage++; if (stage >= NSTG) stage = 0;
    }
    CP_WAIT0();   // drain any remaining async groups before leaving phase
}

// ---------------------------------------------------------------------------
// MEGAKERNEL: prep -> bar -> G1 -> bar -> mid -> bar -> G2
// grid = 148 (co-resident: 1 CTA/SM, 192 KB smem, 512 thr)
// ---------------------------------------------------------------------------
#define PREP_POOL 256
#define PREP_TR   2016        // W1 864 + Wv 576 + Wp 576
#define MID_SM    192         // softmax units (512 rows each)
#define MID_VT    288
#define MID_TOT   (MID_SM + MID_VT)

__global__ void __launch_bounds__(GTHR, 1) megakernel(
    const float* __restrict__ x,  const float* __restrict__ Wa,
    const float* __restrict__ Wb, const float* __restrict__ Wv,
    const float* __restrict__ Wp, const float* __restrict__ bp,
    float* __restrict__ out,
    __half* __restrict__ Xh, __half* __restrict__ xbar,
    __half* __restrict__ W1, __half* __restrict__ WvT, __half* __restrict__ WpT,
    __half* __restrict__ Yh, float* __restrict__ VB,
    __half* __restrict__ P, __half* __restrict__ Vt)
{
    extern __shared__ char dsm[];
    const int tid = threadIdx.x;
    const int bid = blockIdx.x;

    // entry snapshot of release words (safe: flips happen only after all
    // CTAs of this launch pass the corresponding barrier)
    int rel0, rel1, rel2;
    {
        volatile int* rp = g_bar_release;
        rel0 = rp[0]; rel1 = rp[1]; rel2 = rp[2];
    }

    // ---------------- Phase 0: prep ----------------
    // pool+convert units (x read once)
    for (int u = bid; u < PREP_POOL; u += GGRID) {
        const float* base = x + (size_t)u * 32 * KD;
        __half* xh = Xh + (size_t)u * 32 * KD;
        float s0 = 0.f, s1 = 0.f;
        #pragma unroll 4
        for (int r = 0; r < 32; r++) {
            const float* row = base + (size_t)r * KD;
            __half* orow = xh + (size_t)r * KD;
            const float f0 = row[tid];
            s0 += f0;
            orow[tid] = __float2half_rn(f0);
            if (tid < 256) {
                const float f1 = row[512 + tid];
                s1 += f1;
                orow[512 + tid] = __float2half_rn(f1);
            }
        }
        xbar[(size_t)u * KD + tid] = __float2half_rn(s0);
        if (tid < 256)
            xbar[(size_t)u * KD + 512 + tid] = __float2half_rn(s1);
    }

    // weight transposes: 2 tiles of 32x32 per iteration (one per 256-thr half)
    {
        float (*tile2)[32][33] = reinterpret_cast<float (*)[32][33]>(dsm);
        const int q  = tid >> 8;          // half index 0/1
        const int qt = tid & 255;
        const int tx = qt & 31, ty = qt >> 5;  // ty 0..7
        for (int u = bid * 2; u < PREP_TR; u += GGRID * 2) {
            const int unit = u + q;
            const float* W = nullptr;
            __half* T = nullptr;
            int N = 0, nloc = 0, n0 = 0, k0 = 0;
            if (unit < PREP_TR) {
                int tb = unit;
                if (tb < 864) {
                    const int nt = tb % 36, kt = tb / 36;
                    n0 = nt * 32; k0 = kt * 32;
                    T = W1;
                    if (n0 < 768) { W = Wa; N = 768; nloc = n0; }
                    else          { W = Wb; N = 384; nloc = n0 - 768; }
                } else if (tb < 864 + 576) {
                    tb -= 864;
                    const int nt = tb % 24, kt = tb / 24;
                    n0 = nt * 32; k0 = kt * 32;
                    T = WvT; W = Wv; N = 768; nloc = n0;
                } else {
                    tb -= 864 + 576;
                    const int nt = tb % 24, kt = tb / 24;
                    n0 = nt * 32; k0 = kt * 32;
                    T = WpT; W = Wp; N = 768; nloc = n0;
                }
                #pragma unroll
                for (int i = 0; i < 32; i += 8)
                    tile2[q][ty + i][tx] = W[(size_t)(k0 + ty + i) * N + nloc + tx];
            }
            __syncthreads();
            if (unit < PREP_TR) {
                #pragma unroll
                for (int i = 0; i < 32; i += 8)
                    T[(size_t)(n0 + ty + i) * KD + k0 + tx] =
                        __float2half_rn(tile2[q][tx][ty + i]);
            }
            __syncthreads();
        }
    }

    grid_barrier(0, rel0);

    // ---------------- Phase 1: G1 ----------------
    gemm_phase(true, Xh, W1, Yh, xbar, WvT, VB, nullptr, 588,
               smem_u32(dsm), tid, bid);

    grid_barrier(1, rel1);

    // ---------------- Phase 2: mid ----------------
    {
        __half (*Ws)[66] = reinterpret_cast<__half (*)[66]>(dsm);
        float  (*Vs)[68] = reinterpret_cast<float (*)[68]>(dsm + 17408);

        for (int u = bid; u < MID_TOT; u += GGRID) {
            if (u < MID_SM) {
                // softmax over 64 factorized scores for 512 rows
                const int tile = u & 3;
                const int bh   = u >> 2;
                const int h    = bh % NHEAD;
                const int b    = bh / NHEAD;
                const int row  = b * SEQ + tile * 512 + tid;
                const __half* arow = Yh + (size_t)row * NAB + h * NA;
                const __half* brow = Yh + (size_t)row * NAB + DIM + h * NB;

                float bb[NB];
                {
                    const uint4* b4 = (const uint4*)brow;
                    #pragma unroll
                    for (int q8 = 0; q8 < 4; q8++) {
                        uint4 uu = b4[q8];
                        const __half2* hp = (const __half2*)&uu;
                        #pragma unroll
                        for (int q = 0; q < 4; q++) {
                            float2 f = __half22float2(hp[q]);
                            bb[q8 * 8 + q * 2]     = f.x;
                            bb[q8 * 8 + q * 2 + 1] = f.y;
                        }
                    }
                }

                float e[NA];
                float s = 0.f;
                const uint4* a4 = (const uint4*)arow;
                #pragma unroll
                for (int k8 = 0; k8 < 8; k8++) {
                    uint4 uu = a4[k8];
                    const __half2* hp = (const __half2*)&uu;
                    #pragma unroll
                    for (int q = 0; q < 4; q++) {
                        float2 af = __half22float2(hp[q]);
                        const int k = k8 * 8 + q * 2;
                        const float c = bb[k >> 1];
                        e[k]     = __expf(af.x * c);
                        e[k + 1] = __expf(af.y * c);
                        s += e[k] + e[k + 1];
                    }
                }
                const float inv = 1.f / (32.f * s);

                __half2 hv[32];
                #pragma unroll
                for (int k = 0; k < NA; k += 2)
                    hv[k >> 1] = __floats2half2_rn(e[k] * inv, e[k + 1] * inv);
                uint4* dst = (uint4*)(P + (size_t)row * KD + h * NA);
                #pragma unroll
                for (int q = 0; q < 8; q++) dst[q] = ((uint4*)hv)[q];
            } else {
                // Vtilde[b][n0+n][h*64+k]  ([N][K] k-contiguous)
                const int v  = u - MID_SM;
                const int b  = v / 72;
                const int r  = v % 72;
                const int h  = r / 6;
                const int n0 = (r % 6) * 128;

                for (int idx = tid; idx < 128 * 64; idx += GTHR) {
                    const int n = idx >> 6, d = idx & 63;
                    Ws[n][d] = WpT[(size_t)(n0 + n) * KD + h * HD + d];
                }
                for (int idx = tid; idx < 64 * 64; idx += GTHR) {
                    const int k = idx >> 6, d = idx & 63;
                    Vs[k][d] = VB[(size_t)(b * 64 + k) * DIM + h * HD + d];
                }
                __syncthreads();

                const int k  = tid & 63;
                const int ng = tid >> 6;        // 0..7
                const float* vr = Vs[k];
                #pragma unroll 1
                for (int j = 0; j < 16; j++) {
                    const int n = ng * 16 + j;
                    const __half* wr = Ws[n];
                    float acc = 0.f;
                    #pragma unroll
                    for (int d = 0; d < 64; d += 4) {
                        float4 vv = *(const float4*)(vr + d);
                        float2 w0 = __half22float2(*(const __half2*)(wr + d));
                        float2 w1 = __half22float2(*(const __half2*)(wr + d + 2));
                        acc = fmaf(vv.x, w0.x, acc);
                        acc = fmaf(vv.y, w0.y, acc);
                        acc = fmaf(vv.z, w1.x, acc);
                        acc = fmaf(vv.w, w1.y, acc);
                    }
                    Vt[((size_t)b * KD + n0 + n) * KD + h * HD + k] =
                        __float2half_rn(acc);
                }
                __syncthreads();   // before next iteration reuses Ws/Vs
            }
        }
    }

    grid_barrier(2, rel2);

    // ---------------- Phase 3: G2 ----------------
    gemm_phase(false, P, Vt, out, nullptr, nullptr, nullptr, bp, 384,
               smem_u32(dsm), tid, bid);
}

// ---------------------------------------------------------------------------
// Launch
// ---------------------------------------------------------------------------
extern "C" void kernel_launch(void* const* d_in, const int* in_sizes, int n_in,
                              void* d_out, int out_size)
{
    const float* x  = (const float*)d_in[0];
    const float* Wa = (const float*)d_in[1];
    const float* Wb = (const float*)d_in[2];
    const float* Wv = (const float*)d_in[3];
    const float* Wp = (const float*)d_in[4];
    const float* bp = (const float*)d_in[5];
    float* out = (float*)d_out;

    float *vbar;
    __half *yh, *p, *vt, *xh, *xbar, *w1, *wv, *wp;
    cudaGetSymbolAddress((void**)&yh,   g_Yh);
    cudaGetSymbolAddress((void**)&p,    g_P);
    cudaGetSymbolAddress((void**)&vt,   g_Vt);
    cudaGetSymbolAddress((void**)&vbar, g_VBAR);
    cudaGetSymbolAddress((void**)&xh,   g_Xh);
    cudaGetSymbolAddress((void**)&xbar, g_Xbar);
    cudaGetSymbolAddress((void**)&w1,   g_W1);
    cudaGetSymbolAddress((void**)&wv,   g_Wv);
    cudaGetSymbolAddress((void**)&wp,   g_Wp);

    cudaFuncSetAttribute(megakernel,
                         cudaFuncAttributeMaxDynamicSharedMemorySize, GSMEM);

    megakernel<<<GGRID, GTHR, GSMEM>>>(
        x, Wa, Wb, Wv, Wp, bp, out,
        xh, xbar, w1, wv, wp, yh, vbar, p, vt);
}

// round 17
// speedup vs baseline: 1.1641x; 1.1641x over previous
#include <cuda_runtime.h>
#include <cuda_fp16.h>
#include <stdint.h>
#include <math.h>

// ---------------------------------------------------------------------------
// Problem constants
// ---------------------------------------------------------------------------
#define BATCH 4
#define SEQ   2048
#define DIM   768
#define NHEAD 12
#define HD    64
#define NA    64
#define NB    32
#define MROWS 8192
#define KD    768
#define NAB   1152
#define NPOOL 256

// ---------------------------------------------------------------------------
// Static scratch
// ---------------------------------------------------------------------------
__device__ __align__(256) __half g_Yh[MROWS * NAB];      // x@[Wa|Wb] fp16
__device__ __align__(256) __half g_P[MROWS * KD];        // normalized exp-scores
__device__ __align__(256) __half g_Vt[BATCH * KD * KD];  // per-batch Vtilde [n][k]
__device__ __align__(256) float  g_VBAR[NPOOL * DIM];    // pooled-x @ Wv
__device__ __align__(256) __half g_Xh[MROWS * KD];
__device__ __align__(256) __half g_Xbar[NPOOL * KD];
__device__ __align__(256) __half g_W1[NAB * KD];
__device__ __align__(256) __half g_Wv[DIM * KD];
__device__ __align__(256) __half g_Wp[DIM * KD];

// ---------------------------------------------------------------------------
// PTX helpers
// ---------------------------------------------------------------------------
__device__ __forceinline__ uint32_t smem_u32(const void* p) {
    uint32_t a;
    asm("{ .reg .u64 t; cvta.to.shared.u64 t, %1; cvt.u32.u64 %0, t; }"
        : "=r"(a) : "l"(p));
    return a;
}

#define CP16(saddr, gptr) \
    asm volatile("cp.async.cg.shared.global [%0], [%1], 16;" \
                 :: "r"(saddr), "l"(gptr) : "memory")
#define CP_COMMIT() asm volatile("cp.async.commit_group;" ::: "memory")
#define CP_WAIT1()  asm volatile("cp.async.wait_group 1;" ::: "memory")

#define LDM4(r, addr) \
    asm volatile("ldmatrix.sync.aligned.m8n8.x4.shared.b16 {%0,%1,%2,%3}, [%4];" \
                 : "=r"((r)[0]), "=r"((r)[1]), "=r"((r)[2]), "=r"((r)[3]) \
                 : "r"(addr))

// fp32-accumulator MMA
#define MMA(c, a, b0, b1) \
    asm volatile("mma.sync.aligned.m16n8k16.row.col.f32.f16.f16.f32 " \
                 "{%0,%1,%2,%3}, {%4,%5,%6,%7}, {%8,%9}, {%0,%1,%2,%3};" \
                 : "+f"((c)[0]), "+f"((c)[1]), "+f"((c)[2]), "+f"((c)[3]) \
                 : "r"((a)[0]), "r"((a)[1]), "r"((a)[2]), "r"((a)[3]), \
                   "r"(b0), "r"(b1))

// ---------------------------------------------------------------------------
// Prep kernel (R15): fused x convert+pool + weight transposes
// ---------------------------------------------------------------------------
#define PREP_PBLKS   NPOOL
#define PREP_W1BLKS  864
#define PREP_WVBLKS  576
#define PREP_WPBLKS  576
#define PREP_TRBLKS  (PREP_W1BLKS + PREP_WVBLKS + PREP_WPBLKS)
#define PREP_BLKS    (PREP_PBLKS + PREP_TRBLKS)

__global__ __launch_bounds__(256) void prep_kernel(
    const float* __restrict__ x,  const float* __restrict__ Wa,
    const float* __restrict__ Wb, const float* __restrict__ Wv,
    const float* __restrict__ Wp, __half* __restrict__ Xh,
    __half* __restrict__ W1, __half* __restrict__ WvT, __half* __restrict__ WpT,
    __half* __restrict__ xbar)
{
    const int blk = blockIdx.x;
    const int tid = threadIdx.x;

    if (blk < PREP_PBLKS) {
        const int p = blk;
        const float* base = x + (size_t)p * 32 * KD;
        __half* xh = Xh + (size_t)p * 32 * KD;
        float s0 = 0.f, s1 = 0.f, s2 = 0.f;
        #pragma unroll 4
        for (int r = 0; r < 32; r++) {
            const float* row = base + (size_t)r * KD;
            const float f0 = row[tid], f1 = row[tid + 256], f2 = row[tid + 512];
            s0 += f0; s1 += f1; s2 += f2;
            __half* orow = xh + (size_t)r * KD;
            orow[tid]       = __float2half_rn(f0);
            orow[tid + 256] = __float2half_rn(f1);
            orow[tid + 512] = __float2half_rn(f2);
        }
        xbar[(size_t)p * KD + tid]       = __float2half_rn(s0);
        xbar[(size_t)p * KD + tid + 256] = __float2half_rn(s1);
        xbar[(size_t)p * KD + tid + 512] = __float2half_rn(s2);
        return;
    }

    __shared__ float tile[32][33];
    const int tx = tid & 31, ty = tid >> 5;

    const float* W;
    __half* T;
    int N, nloc, n0, k0;
    int tb = blk - PREP_PBLKS;
    if (tb < PREP_W1BLKS) {
        const int nt = tb % 36, kt = tb / 36;
        n0 = nt * 32; k0 = kt * 32;
        T = W1;
        if (n0 < 768) { W = Wa; N = 768; nloc = n0; }
        else          { W = Wb; N = 384; nloc = n0 - 768; }
    } else if (tb < PREP_W1BLKS + PREP_WVBLKS) {
        tb -= PREP_W1BLKS;
        const int nt = tb % 24, kt = tb / 24;
        n0 = nt * 32; k0 = kt * 32;
        T = WvT; W = Wv; N = 768; nloc = n0;
    } else {
        tb -= PREP_W1BLKS + PREP_WVBLKS;
        const int nt = tb % 24, kt = tb / 24;
        n0 = nt * 32; k0 = kt * 32;
        T = WpT; W = Wp; N = 768; nloc = n0;
    }

    #pragma unroll
    for (int i = 0; i < 32; i += 8)
        tile[ty + i][tx] = W[(size_t)(k0 + ty + i) * N + nloc + tx];
    __syncthreads();
    #pragma unroll
    for (int i = 0; i < 32; i += 8)
        T[(size_t)(n0 + ty + i) * KD + k0 + tx] =
            __float2half_rn(tile[tx][ty + i]);
}

// ---------------------------------------------------------------------------
// fp32-acc persistent GEMM: CTA 128x128, 512 thr, 16 warps (4Mx4N, 32x32),
// K-chunk 64, 3-stage 32KB pipeline (prefetch distance 2, wait_group 1,
// ONE sync per chunk), 96 KB smem -> 2 CTAs/SM, grid 304.
// MODE 0: tiles [0,576) Xh@W1 -> Yh fp16; [576,588) Xbar@Wv -> VBAR f32
// MODE 1: tiles [0,384) P@Vt_b + bias -> out f32
// ---------------------------------------------------------------------------
#define KC    64
#define NCHT  12
#define ABUF  16384            // 128 rows x 128 B
#define STG   (2 * ABUF)       // A + B = 32 KB
#define NSTG  3
#define GSMEM (NSTG * STG)     // 96 KB
#define GGRID 304
#define GTHR  512

#define SWZ(row, ch) (((uint32_t)(row) << 7) + ((((uint32_t)(ch)) ^ ((row) & 7)) << 4))

__device__ __forceinline__ void ld_chunk(
    uint32_t sb, const __half* __restrict__ Ag, const __half* __restrict__ Bg,
    int row0, int col0, int kc, int tid)
{
    const int rr = tid >> 2;          // 0..127
    const int c2 = (tid & 3) << 1;    // 0,2,4,6
    const uint32_t s0 = SWZ(rr, c2), s1 = SWZ(rr, c2 + 1);
    const __half* ap = Ag + (size_t)(row0 + rr) * KD + kc + c2 * 8;
    CP16(sb + s0,        ap);
    CP16(sb + s1,        ap + 8);
    const __half* bp = Bg + (size_t)(col0 + rr) * KD + kc + c2 * 8;
    CP16(sb + ABUF + s0, bp);
    CP16(sb + ABUF + s1, bp + 8);
}

template<int MODE>
__global__ void __launch_bounds__(GTHR, 2) gemm_fp16(
    const __half* __restrict__ A0, const __half* __restrict__ B0,
    void* __restrict__ C0v,
    const __half* __restrict__ A1, const __half* __restrict__ B1,
    float* __restrict__ C1,
    const float* __restrict__ bias, int ntiles)
{
    extern __shared__ char dsm[];
    const uint32_t sbase = smem_u32(dsm);

    const int tid  = threadIdx.x;
    const int wid  = tid >> 5;
    const int lane = tid & 31;
    const int m0 = (wid & 3) * 32;
    const int n0 = (wid >> 2) * 32;
    const int lr = lane & 15;
    const int lh = lane >> 4;
    const int r7 = lr & 7;
    const int bid = blockIdx.x;
    const int G   = gridDim.x;

    const int tcount = (bid < ntiles) ? ((ntiles - 1 - bid) / G + 1) : 0;
    if (tcount == 0) return;
    const int total_g = tcount * NCHT;

    auto tmap_load = [&](int t, const __half*& A, const __half*& B,
                         int& row0, int& col0) {
        if (MODE == 0) {
            if (t < 576) { A = A0; B = B0; row0 = (t / 9) << 7; col0 = (t % 9) << 7; }
            else { int tt = t - 576; A = A1; B = B1;
                   row0 = (tt / 6) << 7; col0 = (tt % 6) << 7; }
        } else {
            row0 = (t / 6) << 7; col0 = (t % 6) << 7;
            A = A0; B = B0 + (size_t)(row0 >> 11) * KD * KD;
        }
    };

    uint32_t aRow[2], bRow[2];
    #pragma unroll
    for (int mt = 0; mt < 2; mt++)
        aRow[mt] = sbase + ((uint32_t)(m0 + mt * 16 + lr) << 7);
    #pragma unroll
    for (int nt = 0; nt < 2; nt++)
        bRow[nt] = sbase + ABUF + ((uint32_t)(n0 + nt * 16 + lr) << 7);

    float acc[2][4][4];
    #pragma unroll
    for (int i = 0; i < 2; i++)
        #pragma unroll
        for (int j = 0; j < 4; j++)
            #pragma unroll
            for (int q = 0; q < 4; q++) acc[i][j][q] = 0.f;

    const __half *Ap, *Bp;
    int rowp, colp;
    tmap_load(bid, Ap, Bp, rowp, colp);

    // prologue: chunks 0,1 (prefetch distance 2)
    ld_chunk(sbase,       Ap, Bp, rowp, colp, 0,  tid);
    CP_COMMIT();
    ld_chunk(sbase + STG, Ap, Bp, rowp, colp, KC, tid);
    CP_COMMIT();

    int stage = 0;
    #pragma unroll 1
    for (int g = 0; g < total_g; g++) {
        CP_WAIT1();            // chunk g resident
        __syncthreads();       // all warps done with chunk g-1's stage

        const int g2 = g + 2;
        if (g2 < total_g) {
            const int c2 = g2 % NCHT;
            if (c2 == 0)
                tmap_load(bid + (g2 / NCHT) * G, Ap, Bp, rowp, colp);
            int ws = stage + 2; if (ws >= NSTG) ws -= NSTG;
            ld_chunk(sbase + ws * STG, Ap, Bp, rowp, colp, c2 * KC, tid);
        }
        CP_COMMIT();

        const uint32_t so = (uint32_t)(stage * STG);
        #pragma unroll
        for (int kq = 0; kq < 4; kq++) {
            const uint32_t xp = so + (uint32_t)(((kq * 2 + lh) ^ r7) << 4);
            uint32_t af[2][4], bf[2][4];
            #pragma unroll
            for (int mt = 0; mt < 2; mt++) LDM4(af[mt], aRow[mt] + xp);
            #pragma unroll
            for (int nt = 0; nt < 2; nt++) LDM4(bf[nt], bRow[nt] + xp);
            #pragma unroll
            for (int mt = 0; mt < 2; mt++)
                #pragma unroll
                for (int nt = 0; nt < 2; nt++)
                    #pragma unroll
                    for (int h = 0; h < 2; h++)
                        MMA(acc[mt][nt * 2 + h], af[mt], bf[nt][h], bf[nt][h + 2]);
        }

        if ((g % NCHT) == NCHT - 1) {
            const int t = bid + (g / NCHT) * G;
            const int l4 = lane >> 2;
            const int l2 = (lane & 3) * 2;
            int row0, col0;
            if (MODE == 0 && t < 576) {
                __half* C = (__half*)C0v;
                row0 = (t / 9) << 7; col0 = (t % 9) << 7;
                #pragma unroll
                for (int mt = 0; mt < 2; mt++)
                    #pragma unroll
                    for (int nn = 0; nn < 4; nn++) {
                        const int grow = row0 + m0 + mt * 16 + l4;
                        const int gcol = col0 + n0 + (nn >> 1) * 16 + (nn & 1) * 8 + l2;
                        *(__half2*)(C + (size_t)grow * NAB + gcol) =
                            __floats2half2_rn(acc[mt][nn][0], acc[mt][nn][1]);
                        *(__half2*)(C + (size_t)(grow + 8) * NAB + gcol) =
                            __floats2half2_rn(acc[mt][nn][2], acc[mt][nn][3]);
                        acc[mt][nn][0] = 0.f; acc[mt][nn][1] = 0.f;
                        acc[mt][nn][2] = 0.f; acc[mt][nn][3] = 0.f;
                    }
            } else if (MODE == 0) {
                float* C = C1;
                const int tt = t - 576;
                row0 = (tt / 6) << 7; col0 = (tt % 6) << 7;
                #pragma unroll
                for (int mt = 0; mt < 2; mt++)
                    #pragma unroll
                    for (int nn = 0; nn < 4; nn++) {
                        const int grow = row0 + m0 + mt * 16 + l4;
                        const int gcol = col0 + n0 + (nn >> 1) * 16 + (nn & 1) * 8 + l2;
                        *(float2*)(C + (size_t)grow * DIM + gcol) =
                            make_float2(acc[mt][nn][0], acc[mt][nn][1]);
                        *(float2*)(C + (size_t)(grow + 8) * DIM + gcol) =
                            make_float2(acc[mt][nn][2], acc[mt][nn][3]);
                        acc[mt][nn][0] = 0.f; acc[mt][nn][1] = 0.f;
                        acc[mt][nn][2] = 0.f; acc[mt][nn][3] = 0.f;
                    }
            } else {
                float* C = (float*)C0v;
                row0 = (t / 6) << 7; col0 = (t % 6) << 7;
                #pragma unroll
                for (int mt = 0; mt < 2; mt++)
                    #pragma unroll
                    for (int nn = 0; nn < 4; nn++) {
                        const int grow = row0 + m0 + mt * 16 + l4;
                        const int gcol = col0 + n0 + (nn >> 1) * 16 + (nn & 1) * 8 + l2;
                        const float b0 = bias[gcol], b1 = bias[gcol + 1];
                        *(float2*)(C + (size_t)grow * DIM + gcol) =
                            make_float2(acc[mt][nn][0] + b0, acc[mt][nn][1] + b1);
                        *(float2*)(C + (size_t)(grow + 8) * DIM + gcol) =
                            make_float2(acc[mt][nn][2] + b0, acc[mt][nn][3] + b1);
                        acc[mt][nn][0] = 0.f; acc[mt][nn][1] = 0.f;
                        acc[mt][nn][2] = 0.f; acc[mt][nn][3] = 0.f;
                    }
            }
        }

        stage++; if (stage >= NSTG) stage = 0;
    }
}

// ---------------------------------------------------------------------------
// Mid kernel (R15): softmax -> P; Vtilde[b][n][h*64+k] ([N][K] k-contig)
// ---------------------------------------------------------------------------
#define MID_ATTN 384
#define MID_VT   288
#define MID_BLKS (MID_ATTN + MID_VT)

__global__ __launch_bounds__(256) void mid_kernel(
    const __half* __restrict__ Y, const float* __restrict__ VB,
    const __half* __restrict__ WpT, __half* __restrict__ P,
    __half* __restrict__ Vt)
{
    const int blk = blockIdx.x;
    const int tid = threadIdx.x;

    if (blk < MID_ATTN) {
        const int tile = blk & 7;
        const int bh   = blk >> 3;
        const int h    = bh % NHEAD;
        const int b    = bh / NHEAD;
        const int row  = b * SEQ + tile * 256 + tid;
        const __half* arow = Y + (size_t)row * NAB + h * NA;
        const __half* brow = Y + (size_t)row * NAB + DIM + h * NB;

        float bb[NB];
        {
            const uint4* b4 = (const uint4*)brow;
            #pragma unroll
            for (int q8 = 0; q8 < 4; q8++) {
                uint4 u = b4[q8];
                const __half2* hp = (const __half2*)&u;
                #pragma unroll
                for (int q = 0; q < 4; q++) {
                    float2 f = __half22float2(hp[q]);
                    bb[q8 * 8 + q * 2]     = f.x;
                    bb[q8 * 8 + q * 2 + 1] = f.y;
                }
            }
        }

        float e[NA];
        float s = 0.f;
        const uint4* a4 = (const uint4*)arow;
        #pragma unroll
        for (int k8 = 0; k8 < 8; k8++) {
            uint4 u = a4[k8];
            const __half2* hp = (const __half2*)&u;
            #pragma unroll
            for (int q = 0; q < 4; q++) {
                float2 af = __half22float2(hp[q]);
                const int k = k8 * 8 + q * 2;
                const float c = bb[k >> 1];
                e[k]     = __expf(af.x * c);
                e[k + 1] = __expf(af.y * c);
                s += e[k] + e[k + 1];
            }
        }
        const float inv = 1.f / (32.f * s);

        __half2 hv[32];
        #pragma unroll
        for (int k = 0; k < NA; k += 2)
            hv[k >> 1] = __floats2half2_rn(e[k] * inv, e[k + 1] * inv);
        uint4* dst = (uint4*)(P + (size_t)row * KD + h * NA);
        #pragma unroll
        for (int q = 0; q < 8; q++) dst[q] = ((uint4*)hv)[q];
        return;
    }

    __shared__ __half Ws[128][66];    // [n][d] padded
    __shared__ float  Vs[64][68];     // [k][d] padded (16B-aligned rows)

    const int v  = blk - MID_ATTN;
    const int b  = v / 72;
    const int r  = v % 72;
    const int h  = r / 6;
    const int n0 = (r % 6) * 128;

    for (int idx = tid; idx < 128 * 64; idx += 256) {
        const int n = idx >> 6, d = idx & 63;
        Ws[n][d] = WpT[(size_t)(n0 + n) * KD + h * HD + d];
    }
    for (int idx = tid; idx < 64 * 64; idx += 256) {
        const int k = idx >> 6, d = idx & 63;
        Vs[k][d] = VB[(size_t)(b * 64 + k) * DIM + h * HD + d];
    }
    __syncthreads();

    const int k  = tid & 63;
    const int ng = tid >> 6;
    const float* vr = Vs[k];
    #pragma unroll 1
    for (int j = 0; j < 32; j++) {
        const int n = ng * 32 + j;
        const __half* wr = Ws[n];
        float acc = 0.f;
        #pragma unroll
        for (int d = 0; d < 64; d += 4) {
            float4 vv = *(const float4*)(vr + d);
            float2 w0 = __half22float2(*(const __half2*)(wr + d));
            float2 w1 = __half22float2(*(const __half2*)(wr + d + 2));
            acc = fmaf(vv.x, w0.x, acc);
            acc = fmaf(vv.y, w0.y, acc);
            acc = fmaf(vv.z, w1.x, acc);
            acc = fmaf(vv.w, w1.y, acc);
        }
        Vt[((size_t)b * KD + n0 + n) * KD + h * HD + k] = __float2half_rn(acc);
    }
}

// ---------------------------------------------------------------------------
// Launch
// ---------------------------------------------------------------------------
extern "C" void kernel_launch(void* const* d_in, const int* in_sizes, int n_in,
                              void* d_out, int out_size)
{
    const float* x  = (const float*)d_in[0];
    const float* Wa = (const float*)d_in[1];
    const float* Wb = (const float*)d_in[2];
    const float* Wv = (const float*)d_in[3];
    const float* Wp = (const float*)d_in[4];
    const float* bp = (const float*)d_in[5];
    float* out = (float*)d_out;

    float *vbar;
    __half *yh, *p, *vt, *xh, *xbar, *w1, *wv, *wp;
    cudaGetSymbolAddress((void**)&yh,   g_Yh);
    cudaGetSymbolAddress((void**)&p,    g_P);
    cudaGetSymbolAddress((void**)&vt,   g_Vt);
    cudaGetSymbolAddress((void**)&vbar, g_VBAR);
    cudaGetSymbolAddress((void**)&xh,   g_Xh);
    cudaGetSymbolAddress((void**)&xbar, g_Xbar);
    cudaGetSymbolAddress((void**)&w1,   g_W1);
    cudaGetSymbolAddress((void**)&wv,   g_Wv);
    cudaGetSymbolAddress((void**)&wp,   g_Wp);

    cudaFuncSetAttribute(gemm_fp16<0>,
                         cudaFuncAttributeMaxDynamicSharedMemorySize, GSMEM);
    cudaFuncSetAttribute(gemm_fp16<1>,
                         cudaFuncAttributeMaxDynamicSharedMemorySize, GSMEM);

    prep_kernel<<<PREP_BLKS, 256>>>(x, Wa, Wb, Wv, Wp, xh, w1, wv, wp, xbar);

    // x@[Wa|Wb] -> Yh (576 tiles) + xbar@Wv -> VBAR (12 tiles)
    gemm_fp16<0><<<GGRID, GTHR, GSMEM>>>(xh, w1, yh, xbar, wv, vbar, nullptr, 588);

    // softmax -> P + Vtilde = blockdiag(Vbar) @ Wp
    mid_kernel<<<MID_BLKS, 256>>>(yh, vbar, wp, p, vt);

    // out = P @ Vt_b + bias (384 tiles)
    gemm_fp16<1><<<GGRID, GTHR, GSMEM>>>(p, vt, out, nullptr, nullptr, nullptr, bp, 384);
}